// round 7
// baseline (speedup 1.0000x reference)
#include <cuda_runtime.h>
#include <cuda_bf16.h>
#include <stdint.h>
#include <math.h>

#define N_NODES 8192
#define F_IN    256
#define F_OUT   128

// ---------------- scratch (__device__ globals: allocation-free rule) --------
__device__ float g_Wh[N_NODES * F_OUT];                  // 4 MB
__device__ float g_wh1[N_NODES];
__device__ float g_wh2[N_NODES];
__device__ __nv_bfloat16 g_WhT_hi[F_OUT * N_NODES];      // 2 MB  [c][j]
__device__ __nv_bfloat16 g_WhT_lo[F_OUT * N_NODES];      // 2 MB  [c][j]
__device__ float g_part[2][N_NODES * F_OUT];             // 8 MB partial numerators
__device__ float g_denp[2][N_NODES];                     // partial denominators

// ---------------- helpers ---------------------------------------------------
__device__ __forceinline__ uint32_t smem_u32(const void* p) {
    uint32_t a;
    asm("{ .reg .u64 t; cvta.to.shared.u64 t, %1; cvt.u32.u64 %0, t; }"
        : "=r"(a) : "l"(p));
    return a;
}
__device__ __forceinline__ void ldsm4(uint32_t* r, uint32_t addr) {
    asm volatile("ldmatrix.sync.aligned.m8n8.x4.shared.b16 {%0,%1,%2,%3}, [%4];"
                 : "=r"(r[0]), "=r"(r[1]), "=r"(r[2]), "=r"(r[3]) : "r"(addr));
}
__device__ __forceinline__ void mma16816(float* d, const uint32_t* a,
                                         const uint32_t* b) {
    asm volatile(
        "mma.sync.aligned.m16n8k16.row.col.f32.bf16.bf16.f32 "
        "{%0,%1,%2,%3}, {%4,%5,%6,%7}, {%8,%9}, {%0,%1,%2,%3};"
        : "+f"(d[0]), "+f"(d[1]), "+f"(d[2]), "+f"(d[3])
        : "r"(a[0]), "r"(a[1]), "r"(a[2]), "r"(a[3]), "r"(b[0]), "r"(b[1]));
}
__device__ __forceinline__ uint32_t pack2(float lo, float hi) {
    uint32_t r;
    asm("cvt.rn.bf16x2.f32 %0, %1, %2;" : "=r"(r) : "f"(hi), "f"(lo));
    return r;
}
__device__ __forceinline__ void cpasync16(uint32_t dst, const void* src) {
    asm volatile("cp.async.cg.shared.global [%0], [%1], 16;"
                 :: "r"(dst), "l"(src));
}
__device__ __forceinline__ void cpcommit() {
    asm volatile("cp.async.commit_group;");
}
__device__ __forceinline__ void cpwait0() {
    asm volatile("cp.async.wait_group 0;");
}

// ---------------------------------------------------------------------------
// k1: Wh = h @ W ; fused epilogue computes wh1 = Wh.a1, wh2 = Wh.a2
// ---------------------------------------------------------------------------
__global__ void __launch_bounds__(256) k1_gemm(const float* __restrict__ h,
                                               const float* __restrict__ W,
                                               const float* __restrict__ a) {
    __shared__ float sA[16][64];
    __shared__ float sB[16][128];
    const int t  = threadIdx.x;
    const int ty = t >> 4;
    const int tx = t & 15;
    const int row0 = blockIdx.x * 64;

    float acc[4][8];
#pragma unroll
    for (int m = 0; m < 4; m++)
#pragma unroll
        for (int n = 0; n < 8; n++) acc[m][n] = 0.f;

    for (int k0 = 0; k0 < F_IN; k0 += 16) {
#pragma unroll
        for (int it = 0; it < 4; it++) {
            int idx = t + it * 256;
            int r = idx >> 4, kk = idx & 15;
            sA[kk][r] = h[(row0 + r) * F_IN + k0 + kk];
        }
#pragma unroll
        for (int it = 0; it < 8; it++) {
            int idx = t + it * 256;
            int kk = idx >> 7, c = idx & 127;
            sB[kk][c] = W[(k0 + kk) * F_OUT + c];
        }
        __syncthreads();
#pragma unroll
        for (int kk = 0; kk < 16; kk++) {
            float av[4], bv[8];
#pragma unroll
            for (int m = 0; m < 4; m++) av[m] = sA[kk][ty * 4 + m];
#pragma unroll
            for (int n = 0; n < 8; n++) bv[n] = sB[kk][tx * 8 + n];
#pragma unroll
            for (int m = 0; m < 4; m++)
#pragma unroll
                for (int n = 0; n < 8; n++) acc[m][n] += av[m] * bv[n];
        }
        __syncthreads();
    }
    float a1v[8], a2v[8];
#pragma unroll
    for (int n = 0; n < 8; n++) {
        a1v[n] = a[tx * 8 + n];
        a2v[n] = a[F_OUT + tx * 8 + n];
    }
#pragma unroll
    for (int m = 0; m < 4; m++) {
        int r = row0 + ty * 4 + m;
#pragma unroll
        for (int n = 0; n < 8; n++)
            g_Wh[r * F_OUT + tx * 8 + n] = acc[m][n];
        float p1 = 0.f, p2 = 0.f;
#pragma unroll
        for (int n = 0; n < 8; n++) {
            p1 += acc[m][n] * a1v[n];
            p2 += acc[m][n] * a2v[n];
        }
#pragma unroll
        for (int off = 8; off > 0; off >>= 1) {
            p1 += __shfl_down_sync(0xffffffffu, p1, off);
            p2 += __shfl_down_sync(0xffffffffu, p2, off);
        }
        if (tx == 0) { g_wh1[r] = p1; g_wh2[r] = p2; }
    }
}

// ---------------------------------------------------------------------------
// k2: transpose Wh -> WhT and split fp32 = bf16_hi + bf16_lo
// ---------------------------------------------------------------------------
__global__ void __launch_bounds__(256) k2_transpose() {
    __shared__ float tile[32][33];
    const int tx = threadIdx.x & 31;
    const int ty = threadIdx.x >> 5;
    const int nb = blockIdx.x * 32;
    const int fb = blockIdx.y * 32;
#pragma unroll
    for (int rr = ty; rr < 32; rr += 8)
        tile[rr][tx] = g_Wh[(nb + rr) * F_OUT + fb + tx];
    __syncthreads();
#pragma unroll
    for (int rr = ty; rr < 32; rr += 8) {
        float v = tile[tx][rr];
        __nv_bfloat16 hb = __float2bfloat16(v);
        float hf = __bfloat162float(hb);
        __nv_bfloat16 lb = __float2bfloat16(v - hf);
        size_t o = (size_t)(fb + rr) * N_NODES + nb + tx;
        g_WhT_hi[o] = hb;
        g_WhT_lo[o] = lb;
    }
}

// ---------------------------------------------------------------------------
// k3: fused attention, cp.async double-buffered pipeline, BK=64, 64 chunks
// grid = 128 = 64 row-blocks x 2 j-splits; 1 CTA/SM, 256 threads
// ---------------------------------------------------------------------------
#define BK 64
#define NCHUNK 64
#define TSTRIDE 144                       // 64*2 + 16 pad: ldsm conflict-free
#define TILE_BYTES (128 * TSTRIDE)        // 18432
#define STAGE_BYTES (4 * TILE_BYTES)      // 73728
#define OFF_SHI(s) ((s) * STAGE_BYTES)
#define OFF_SLO(s) ((s) * STAGE_BYTES + TILE_BYTES)
#define OFF_BHI(s) ((s) * STAGE_BYTES + 2 * TILE_BYTES)
#define OFF_BLO(s) ((s) * STAGE_BYTES + 3 * TILE_BYTES)
#define OFF_ADJ(s) (2 * STAGE_BYTES + (s) * 32768)       // 128 rows * 256 B
#define OFF_WH2    (2 * STAGE_BYTES + 2 * 32768)         // 212992
#define SMEM3      (OFF_WH2 + 4096 * 4)                  // 229376

__global__ void __launch_bounds__(256, 1)
k3_attn(const int* __restrict__ adj) {
    extern __shared__ __align__(128) char sm[];
    const uint32_t sbase = smem_u32(sm);
    const int t   = threadIdx.x;
    const int wid = t >> 5;
    const int lid = t & 31;
    const int rb    = blockIdx.x >> 1;
    const int split = blockIdx.x & 1;
    const int row0  = rb * 128;
    const int jg0   = split * 4096;

    float* sWh2 = (float*)(sm + OFF_WH2);
#pragma unroll
    for (int i = 0; i < 16; i++)
        sWh2[t + i * 256] = g_wh2[jg0 + t + i * 256];

    // ---- copy-stage mapping (cp.async): thread t copies row t>>1 ----
    const int cr  = t >> 1;
    const int chq = t & 1;
    const char* srcHiB = (const char*)(g_WhT_hi + (size_t)cr * N_NODES + jg0);
    const char* srcLoB = (const char*)(g_WhT_lo + (size_t)cr * N_NODES + jg0);
    const char* srcAdj = (const char*)(adj + (size_t)(row0 + cr) * N_NODES + jg0);

    // ---- gen-stage mapping: thread owns cols jl0..jl0+3, rows base_r+16i ----
    const int lane16 = t & 15;
    const int jl0    = lane16 * 4;
    const int base_r = t >> 4;            // 0..15
    float wh1v[8], den[8];
#pragma unroll
    for (int i = 0; i < 8; i++) {
        wh1v[i] = g_wh1[row0 + base_r + 16 * i];
        den[i] = 0.f;
    }

    // ---- mma-stage mapping: 8 warps = 2(m) x 4(n); warp tile 64x32 ----
    const int warp_m = wid >> 2;
    const int warp_n = wid & 3;
    float d[4][4][4];
#pragma unroll
    for (int mf = 0; mf < 4; mf++)
#pragma unroll
        for (int nf = 0; nf < 4; nf++)
#pragma unroll
            for (int q = 0; q < 4; q++) d[mf][nf][q] = 0.f;

    const int g = lid >> 3;
    const uint32_t aLane = (uint32_t)((g & 1) * 8 + (lid & 7)) * TSTRIDE
                         + (uint32_t)((g >> 1) * 8) * 2;
    const uint32_t bLane = (uint32_t)((g >> 1) * 8 + (lid & 7)) * TSTRIDE
                         + (uint32_t)((g & 1) * 8) * 2;
    const uint32_t aBase = sbase + (uint32_t)(warp_m * 64) * TSTRIDE + aLane;
    const uint32_t bBase = sbase + (uint32_t)(warp_n * 32) * TSTRIDE + bLane;

    // ---- prologue: async-copy chunk 0 into stage 0 ----
    {
        const uint32_t dB = sbase + (uint32_t)cr * TSTRIDE + (uint32_t)chq * 64;
#pragma unroll
        for (int q = 0; q < 4; q++) {
            cpasync16(dB + OFF_BHI(0) + q * 16, srcHiB + chq * 64 + q * 16);
            cpasync16(dB + OFF_BLO(0) + q * 16, srcLoB + chq * 64 + q * 16);
        }
        const uint32_t dA = sbase + OFF_ADJ(0) + (uint32_t)cr * 256
                          + (uint32_t)chq * 128;
#pragma unroll
        for (int q = 0; q < 8; q++)
            cpasync16(dA + q * 16, srcAdj + chq * 128 + q * 16);
        cpcommit();
    }

    for (int c = 0; c < NCHUNK; c++) {
        const int s = c & 1;
        cpwait0();
        __syncthreads();

        // ---- gen: scores from staged adj ----
        {
            const float4 w4 = *(const float4*)&sWh2[c * BK + jl0];
            const uint32_t adjb = sbase + OFF_ADJ(s) + (uint32_t)lane16 * 16;
            const uint32_t srow = sbase + (uint32_t)jl0 * 2;
#pragma unroll
            for (int i = 0; i < 8; i++) {
                const int rr = base_r + 16 * i;
                int4 av;
                asm volatile("ld.shared.v4.b32 {%0,%1,%2,%3}, [%4];"
                             : "=r"(av.x), "=r"(av.y), "=r"(av.z), "=r"(av.w)
                             : "r"(adjb + (uint32_t)rr * 256));
                const float w1 = wh1v[i];
                float e0 = w1 + w4.x, e1 = w1 + w4.y;
                float e2 = w1 + w4.z, e3 = w1 + w4.w;
                e0 = fmaxf(e0, 0.2f * e0); e1 = fmaxf(e1, 0.2f * e1);
                e2 = fmaxf(e2, 0.2f * e2); e3 = fmaxf(e3, 0.2f * e3);
                float s0 = (av.x > 0) ? __expf(e0) : 0.f;
                float s1 = (av.y > 0) ? __expf(e1) : 0.f;
                float s2 = (av.z > 0) ? __expf(e2) : 0.f;
                float s3 = (av.w > 0) ? __expf(e3) : 0.f;
                den[i] += (s0 + s1) + (s2 + s3);
                uint32_t h01 = pack2(s0, s1), h23 = pack2(s2, s3);
                float f0 = __uint_as_float(h01 << 16);
                float f1 = __uint_as_float(h01 & 0xFFFF0000u);
                float f2 = __uint_as_float(h23 << 16);
                float f3 = __uint_as_float(h23 & 0xFFFF0000u);
                uint32_t l01 = pack2(s0 - f0, s1 - f1);
                uint32_t l23 = pack2(s2 - f2, s3 - f3);
                const uint32_t o = srow + (uint32_t)rr * TSTRIDE;
                asm volatile("st.shared.v2.b32 [%0], {%1,%2};"
                             :: "r"(o + OFF_SHI(s)), "r"(h01), "r"(h23));
                asm volatile("st.shared.v2.b32 [%0], {%1,%2};"
                             :: "r"(o + OFF_SLO(s)), "r"(l01), "r"(l23));
            }
        }
        __syncthreads();

        // ---- issue async copy of chunk c+1 (overlaps MMA below) ----
        if (c + 1 < NCHUNK) {
            const int s1 = (c + 1) & 1;
            const size_t go = (size_t)(c + 1) * BK;
            const uint32_t dB = sbase + (uint32_t)cr * TSTRIDE
                              + (uint32_t)chq * 64;
#pragma unroll
            for (int q = 0; q < 4; q++) {
                cpasync16(dB + OFF_BHI(s1) + q * 16,
                          srcHiB + go * 2 + chq * 64 + q * 16);
                cpasync16(dB + OFF_BLO(s1) + q * 16,
                          srcLoB + go * 2 + chq * 64 + q * 16);
            }
            const uint32_t dA = sbase + OFF_ADJ(s1) + (uint32_t)cr * 256
                              + (uint32_t)chq * 128;
#pragma unroll
            for (int q = 0; q < 8; q++)
                cpasync16(dA + q * 16, srcAdj + go * 4 + chq * 128 + q * 16);
            cpcommit();
        }

        // ---- MMA: D += Shi*Bhi + Shi*Blo + Slo*Bhi ----
#pragma unroll
        for (int ks = 0; ks < 4; ks++) {
            uint32_t ahi[4][4], alo[4][4], bhi[2][4], blo[2][4];
#pragma unroll
            for (int mf = 0; mf < 4; mf++) {
                uint32_t ad = aBase + (uint32_t)(mf * 16) * TSTRIDE + ks * 32;
                ldsm4(ahi[mf], ad + OFF_SHI(s));
                ldsm4(alo[mf], ad + OFF_SLO(s));
            }
#pragma unroll
            for (int nf2 = 0; nf2 < 2; nf2++) {
                uint32_t bd = bBase + (uint32_t)(nf2 * 16) * TSTRIDE + ks * 32;
                ldsm4(bhi[nf2], bd + OFF_BHI(s));
                ldsm4(blo[nf2], bd + OFF_BLO(s));
            }
#pragma unroll
            for (int mf = 0; mf < 4; mf++)
#pragma unroll
                for (int nf = 0; nf < 4; nf++)
                    mma16816(d[mf][nf], ahi[mf], &bhi[nf >> 1][(nf & 1) * 2]);
#pragma unroll
            for (int mf = 0; mf < 4; mf++)
#pragma unroll
                for (int nf = 0; nf < 4; nf++)
                    mma16816(d[mf][nf], ahi[mf], &blo[nf >> 1][(nf & 1) * 2]);
#pragma unroll
            for (int mf = 0; mf < 4; mf++)
#pragma unroll
                for (int nf = 0; nf < 4; nf++)
                    mma16816(d[mf][nf], alo[mf], &bhi[nf >> 1][(nf & 1) * 2]);
        }
        __syncthreads();
    }

    // ---- partial denominator: reduce across the 16 lanes of each row group ----
#pragma unroll
    for (int i = 0; i < 8; i++) {
#pragma unroll
        for (int off = 8; off > 0; off >>= 1)
            den[i] += __shfl_xor_sync(0xffffffffu, den[i], off);
        if (lane16 == 0)
            g_denp[split][row0 + base_r + 16 * i] = den[i];
    }

    // ---- partial numerator: register tiles -> g_part ----
    const int qr = lid >> 2;
    const int qc = (lid & 3) * 2;
    float* base = g_part[split] + (size_t)(row0 + warp_m * 64 + qr) * F_OUT
                + warp_n * 32 + qc;
#pragma unroll
    for (int mf = 0; mf < 4; mf++) {
#pragma unroll
        for (int nf = 0; nf < 4; nf++) {
            float* p = base + (size_t)(mf * 16) * F_OUT + nf * 8;
            *(float2*)p = make_float2(d[mf][nf][0], d[mf][nf][1]);
            *(float2*)(p + 8 * F_OUT) = make_float2(d[mf][nf][2], d[mf][nf][3]);
        }
    }
}

// ---------------------------------------------------------------------------
// k4: combine splits, divide, ELU
// ---------------------------------------------------------------------------
__global__ void __launch_bounds__(256) k4_combine(float* __restrict__ out) {
    int tid = blockIdx.x * 256 + threadIdx.x;
    int e = tid * 8;
    int row = e >> 7;
    float dinv = 1.0f / (g_denp[0][row] + g_denp[1][row]);
    const float4* p0 = (const float4*)(g_part[0] + e);
    const float4* p1 = (const float4*)(g_part[1] + e);
    float4* o = (float4*)(out + e);
#pragma unroll
    for (int q = 0; q < 2; q++) {
        float4 x = p0[q], y = p1[q];
        float v0 = (x.x + y.x) * dinv;
        float v1 = (x.y + y.y) * dinv;
        float v2 = (x.z + y.z) * dinv;
        float v3 = (x.w + y.w) * dinv;
        float4 r;
        r.x = (v0 > 0.f) ? v0 : expm1f(v0);
        r.y = (v1 > 0.f) ? v1 : expm1f(v1);
        r.z = (v2 > 0.f) ? v2 : expm1f(v2);
        r.w = (v3 > 0.f) ? v3 : expm1f(v3);
        o[q] = r;
    }
}

// ---------------------------------------------------------------------------
extern "C" void kernel_launch(void* const* d_in, const int* in_sizes, int n_in,
                              void* d_out, int out_size) {
    const float* h   = (const float*)d_in[0];
    const int*   adj = (const int*)  d_in[1];
    const float* W   = (const float*)d_in[2];
    const float* a   = (const float*)d_in[3];
    float* out = (float*)d_out;

    cudaFuncSetAttribute(k3_attn, cudaFuncAttributeMaxDynamicSharedMemorySize, SMEM3);

    k1_gemm<<<N_NODES / 64, 256>>>(h, W, a);
    k2_transpose<<<dim3(N_NODES / 32, F_OUT / 32), 256>>>();
    k3_attn<<<128, 256, SMEM3>>>(adj);
    k4_combine<<<512, 256>>>(out);
}

// round 11
// speedup vs baseline: 1.8495x; 1.8495x over previous
#include <cuda_runtime.h>
#include <cuda_fp16.h>
#include <stdint.h>
#include <math.h>

#define N_NODES 8192
#define F_IN    256
#define F_OUT   128

// ---------------- scratch (__device__ globals: allocation-free rule) --------
__device__ float g_Wh[N_NODES * F_OUT];                  // 4 MB
__device__ float g_wh1[N_NODES];
__device__ float g_wh2[N_NODES];
__device__ __half g_WhT_hi[F_OUT * N_NODES];             // 2 MB  [c][j]
__device__ __half g_WhT_lo[F_OUT * N_NODES];             // 2 MB  [c][j]
__device__ float g_part[2][N_NODES * F_OUT];             // 8 MB partial numerators
__device__ float g_denp[2][N_NODES];                     // partial denominators

// ---------------- helpers ---------------------------------------------------
__device__ __forceinline__ uint32_t smem_u32(const void* p) {
    uint32_t a;
    asm("{ .reg .u64 t; cvta.to.shared.u64 t, %1; cvt.u32.u64 %0, t; }"
        : "=r"(a) : "l"(p));
    return a;
}
__device__ __forceinline__ void ldsm4(uint32_t* r, uint32_t addr) {
    asm volatile("ldmatrix.sync.aligned.m8n8.x4.shared.b16 {%0,%1,%2,%3}, [%4];"
                 : "=r"(r[0]), "=r"(r[1]), "=r"(r[2]), "=r"(r[3]) : "r"(addr));
}
__device__ __forceinline__ void mma16816(float* d, const uint32_t* a,
                                         const uint32_t* b) {
    asm volatile(
        "mma.sync.aligned.m16n8k16.row.col.f32.f16.f16.f32 "
        "{%0,%1,%2,%3}, {%4,%5,%6,%7}, {%8,%9}, {%0,%1,%2,%3};"
        : "+f"(d[0]), "+f"(d[1]), "+f"(d[2]), "+f"(d[3])
        : "r"(a[0]), "r"(a[1]), "r"(a[2]), "r"(a[3]), "r"(b[0]), "r"(b[1]));
}
// pack two floats -> f16x2 (first arg = low half)
__device__ __forceinline__ uint32_t pack2h(float lo, float hi) {
    uint32_t r;
    asm("cvt.rn.f16x2.f32 %0, %1, %2;" : "=r"(r) : "f"(hi), "f"(lo));
    return r;
}

// ---------------------------------------------------------------------------
// k1: Wh = h @ W ; fused epilogue computes wh1 = Wh.a1, wh2 = Wh.a2
// ---------------------------------------------------------------------------
__global__ void __launch_bounds__(256) k1_gemm(const float* __restrict__ h,
                                               const float* __restrict__ W,
                                               const float* __restrict__ a) {
    __shared__ float sA[16][64];
    __shared__ float sB[16][128];
    const int t  = threadIdx.x;
    const int ty = t >> 4;
    const int tx = t & 15;
    const int row0 = blockIdx.x * 64;

    float acc[4][8];
#pragma unroll
    for (int m = 0; m < 4; m++)
#pragma unroll
        for (int n = 0; n < 8; n++) acc[m][n] = 0.f;

    for (int k0 = 0; k0 < F_IN; k0 += 16) {
#pragma unroll
        for (int it = 0; it < 4; it++) {
            int idx = t + it * 256;
            int r = idx >> 4, kk = idx & 15;
            sA[kk][r] = h[(row0 + r) * F_IN + k0 + kk];
        }
#pragma unroll
        for (int it = 0; it < 8; it++) {
            int idx = t + it * 256;
            int kk = idx >> 7, c = idx & 127;
            sB[kk][c] = W[(k0 + kk) * F_OUT + c];
        }
        __syncthreads();
#pragma unroll
        for (int kk = 0; kk < 16; kk++) {
            float av[4], bv[8];
#pragma unroll
            for (int m = 0; m < 4; m++) av[m] = sA[kk][ty * 4 + m];
#pragma unroll
            for (int n = 0; n < 8; n++) bv[n] = sB[kk][tx * 8 + n];
#pragma unroll
            for (int m = 0; m < 4; m++)
#pragma unroll
                for (int n = 0; n < 8; n++) acc[m][n] += av[m] * bv[n];
        }
        __syncthreads();
    }
    float a1v[8], a2v[8];
#pragma unroll
    for (int n = 0; n < 8; n++) {
        a1v[n] = a[tx * 8 + n];
        a2v[n] = a[F_OUT + tx * 8 + n];
    }
#pragma unroll
    for (int m = 0; m < 4; m++) {
        int r = row0 + ty * 4 + m;
#pragma unroll
        for (int n = 0; n < 8; n++)
            g_Wh[r * F_OUT + tx * 8 + n] = acc[m][n];
        float p1 = 0.f, p2 = 0.f;
#pragma unroll
        for (int n = 0; n < 8; n++) {
            p1 += acc[m][n] * a1v[n];
            p2 += acc[m][n] * a2v[n];
        }
#pragma unroll
        for (int off = 8; off > 0; off >>= 1) {
            p1 += __shfl_down_sync(0xffffffffu, p1, off);
            p2 += __shfl_down_sync(0xffffffffu, p2, off);
        }
        if (tx == 0) { g_wh1[r] = p1; g_wh2[r] = p2; }
    }
}

// ---------------------------------------------------------------------------
// k2: transpose Wh -> WhT and split fp32 = fp16_hi + fp16_lo
// ---------------------------------------------------------------------------
__global__ void __launch_bounds__(256) k2_transpose() {
    __shared__ float tile[32][33];
    const int tx = threadIdx.x & 31;
    const int ty = threadIdx.x >> 5;
    const int nb = blockIdx.x * 32;
    const int fb = blockIdx.y * 32;
#pragma unroll
    for (int rr = ty; rr < 32; rr += 8)
        tile[rr][tx] = g_Wh[(nb + rr) * F_OUT + fb + tx];
    __syncthreads();
#pragma unroll
    for (int rr = ty; rr < 32; rr += 8) {
        float v = tile[tx][rr];
        __half hb = __float2half_rn(v);
        float hf = __half2float(hb);
        __half lb = __float2half_rn(v - hf);
        size_t o = (size_t)(fb + rr) * N_NODES + nb + tx;
        g_WhT_hi[o] = hb;
        g_WhT_lo[o] = lb;
    }
}

// ---------------------------------------------------------------------------
// k3: fused masked-softmax attention on mma.sync (fp16 2-pass split)
// grid = 128 = 64 row-blocks x 2 j-splits; BM=128, BK=128 per chunk
// SMEM tiles padded to 272B rows: 272 mod 128 = 16 -> ldmatrix conflict-free.
// ---------------------------------------------------------------------------
#define BK 128
#define NCHUNK 32
#define TSTRIDE 272                       // bytes per tile row (128*2 + 16)
#define TILE_BYTES (128 * TSTRIDE)        // 34816
#define OFF_S    0
#define OFF_BHI  (OFF_S + TILE_BYTES)
#define OFF_BLO  (OFF_BHI + TILE_BYTES)
#define OFF_WH2  (OFF_BLO + TILE_BYTES)
#define SMEM3    (OFF_WH2 + 4096 * 4)     // 120,832 B

__global__ void __launch_bounds__(256, 1)
k3_attn(const int* __restrict__ adj) {
    extern __shared__ __align__(128) char sm[];
    const uint32_t sbase = smem_u32(sm);
    const int t   = threadIdx.x;
    const int wid = t >> 5;
    const int lid = t & 31;
    const int rb    = blockIdx.x >> 1;
    const int split = blockIdx.x & 1;
    const int row0  = rb * 128;
    const int jg0   = split * 4096;

    float* sWh2 = (float*)(sm + OFF_WH2);
#pragma unroll
    for (int i = 0; i < 16; i++)
        sWh2[t + i * 256] = g_wh2[jg0 + t + i * 256];

    // ---- generation-stage mapping: thread -> (row r, j-half) ----
    const int r    = t >> 1;
    const int half = t & 1;
    const int jb   = half * 64;
    const float wh1r = g_wh1[row0 + r];
    float den = 0.f;

    const __half* srcHi = g_WhT_hi + (size_t)r * N_NODES + jg0 + jb;
    const __half* srcLo = g_WhT_lo + (size_t)r * N_NODES + jg0 + jb;
    const int* adjp = adj + (size_t)(row0 + r) * N_NODES + jg0 + jb;
    const uint32_t genRow = (uint32_t)r * TSTRIDE;

    // ---- mma-stage mapping: 8 warps = 2(m) x 4(n); warp tile 64x32 ----
    const int warp_m = wid >> 2;
    const int warp_n = wid & 3;
    float d[4][4][4];
#pragma unroll
    for (int mf = 0; mf < 4; mf++)
#pragma unroll
        for (int nf = 0; nf < 4; nf++)
#pragma unroll
            for (int q = 0; q < 4; q++) d[mf][nf][q] = 0.f;

    // ldmatrix per-lane address components
    const int g = lid >> 3;
    const uint32_t aLane = (uint32_t)((g & 1) * 8 + (lid & 7)) * TSTRIDE
                         + (uint32_t)((g >> 1) * 8) * 2;
    const uint32_t bLane = (uint32_t)((g >> 1) * 8 + (lid & 7)) * TSTRIDE
                         + (uint32_t)((g & 1) * 8) * 2;
    const uint32_t aBase = sbase + (uint32_t)(warp_m * 64) * TSTRIDE + aLane;
    const uint32_t bBase = sbase + (uint32_t)(warp_n * 32) * TSTRIDE + bLane;

    __syncthreads();

    for (int c = 0; c < NCHUNK; c++) {
        // ---- Stage A: B tiles (WhT hi/lo) + S tile (fp16 scores) ----
#pragma unroll
        for (int kk = 0; kk < 8; kk++) {
            uint4 vh = *(const uint4*)(srcHi + (size_t)c * BK + kk * 8);
            uint4 vl = *(const uint4*)(srcLo + (size_t)c * BK + kk * 8);
            uint32_t o = genRow + (uint32_t)(jb + kk * 8) * 2;
            *(uint4*)(sm + OFF_BHI + o) = vh;
            *(uint4*)(sm + OFF_BLO + o) = vl;
        }
#pragma unroll
        for (int kk = 0; kk < 16; kk++) {
            int4 av = *(const int4*)(adjp + (size_t)c * BK + kk * 4);
            int jl = jb + kk * 4;
            float w0 = sWh2[c * BK + jl + 0], w1 = sWh2[c * BK + jl + 1];
            float w2 = sWh2[c * BK + jl + 2], w3 = sWh2[c * BK + jl + 3];
            float e0 = wh1r + w0, e1 = wh1r + w1, e2 = wh1r + w2, e3 = wh1r + w3;
            e0 = fmaxf(e0, 0.2f * e0); e1 = fmaxf(e1, 0.2f * e1);
            e2 = fmaxf(e2, 0.2f * e2); e3 = fmaxf(e3, 0.2f * e3);
            float s0 = (av.x > 0) ? __expf(e0) : 0.f;
            float s1 = (av.y > 0) ? __expf(e1) : 0.f;
            float s2 = (av.z > 0) ? __expf(e2) : 0.f;
            float s3 = (av.w > 0) ? __expf(e3) : 0.f;
            den += (s0 + s1) + (s2 + s3);
            uint32_t h01 = pack2h(s0, s1), h23 = pack2h(s2, s3);
            uint32_t o = genRow + (uint32_t)jl * 2;
            asm volatile("st.shared.v2.b32 [%0], {%1,%2};"
                         :: "r"(sbase + OFF_S + o), "r"(h01), "r"(h23));
        }
        __syncthreads();

        // ---- Stage B: D += S*Bhi + S*Blo ----
#pragma unroll
        for (int ks = 0; ks < 8; ks++) {
            uint32_t as[4][4], bhi[2][4], blo[2][4];
#pragma unroll
            for (int mf = 0; mf < 4; mf++) {
                uint32_t ad = aBase + (uint32_t)(mf * 16) * TSTRIDE + ks * 32;
                ldsm4(as[mf], ad + OFF_S);
            }
#pragma unroll
            for (int nf2 = 0; nf2 < 2; nf2++) {
                uint32_t bd = bBase + (uint32_t)(nf2 * 16) * TSTRIDE + ks * 32;
                ldsm4(bhi[nf2], bd + OFF_BHI);
                ldsm4(blo[nf2], bd + OFF_BLO);
            }
#pragma unroll
            for (int mf = 0; mf < 4; mf++)
#pragma unroll
                for (int nf = 0; nf < 4; nf++)
                    mma16816(d[mf][nf], as[mf], &bhi[nf >> 1][(nf & 1) * 2]);
#pragma unroll
            for (int mf = 0; mf < 4; mf++)
#pragma unroll
                for (int nf = 0; nf < 4; nf++)
                    mma16816(d[mf][nf], as[mf], &blo[nf >> 1][(nf & 1) * 2]);
        }
        __syncthreads();
    }

    // ---- partial denominator (combine j-halves within lane pair) ----
    float dsum = den + __shfl_xor_sync(0xffffffffu, den, 1);
    if (half == 0) g_denp[split][row0 + r] = dsum;

    // ---- partial numerator: register tiles -> g_part ----
    const int qr = lid >> 2;             // 0..7
    const int qc = (lid & 3) * 2;
    float* base = g_part[split] + (size_t)(row0 + warp_m * 64 + qr) * F_OUT
                + warp_n * 32 + qc;
#pragma unroll
    for (int mf = 0; mf < 4; mf++) {
#pragma unroll
        for (int nf = 0; nf < 4; nf++) {
            float* p = base + (size_t)(mf * 16) * F_OUT + nf * 8;
            *(float2*)p = make_float2(d[mf][nf][0], d[mf][nf][1]);
            *(float2*)(p + 8 * F_OUT) = make_float2(d[mf][nf][2], d[mf][nf][3]);
        }
    }
}

// ---------------------------------------------------------------------------
// k4: combine splits, divide, ELU
// ---------------------------------------------------------------------------
__global__ void __launch_bounds__(256) k4_combine(float* __restrict__ out) {
    int tid = blockIdx.x * 256 + threadIdx.x;
    int e = tid * 8;
    int row = e >> 7;
    float dinv = 1.0f / (g_denp[0][row] + g_denp[1][row]);
    const float4* p0 = (const float4*)(g_part[0] + e);
    const float4* p1 = (const float4*)(g_part[1] + e);
    float4* o = (float4*)(out + e);
#pragma unroll
    for (int q = 0; q < 2; q++) {
        float4 x = p0[q], y = p1[q];
        float v0 = (x.x + y.x) * dinv;
        float v1 = (x.y + y.y) * dinv;
        float v2 = (x.z + y.z) * dinv;
        float v3 = (x.w + y.w) * dinv;
        float4 r;
        r.x = (v0 > 0.f) ? v0 : expm1f(v0);
        r.y = (v1 > 0.f) ? v1 : expm1f(v1);
        r.z = (v2 > 0.f) ? v2 : expm1f(v2);
        r.w = (v3 > 0.f) ? v3 : expm1f(v3);
        o[q] = r;
    }
}

// ---------------------------------------------------------------------------
extern "C" void kernel_launch(void* const* d_in, const int* in_sizes, int n_in,
                              void* d_out, int out_size) {
    const float* h   = (const float*)d_in[0];
    const int*   adj = (const int*)  d_in[1];
    const float* W   = (const float*)d_in[2];
    const float* a   = (const float*)d_in[3];
    float* out = (float*)d_out;

    cudaFuncSetAttribute(k3_attn, cudaFuncAttributeMaxDynamicSharedMemorySize, SMEM3);

    k1_gemm<<<N_NODES / 64, 256>>>(h, W, a);
    k2_transpose<<<dim3(N_NODES / 32, F_OUT / 32), 256>>>();
    k3_attn<<<128, 256, SMEM3>>>(adj);
    k4_combine<<<512, 256>>>(out);
}

// round 14
// speedup vs baseline: 2.3799x; 1.2868x over previous
#include <cuda_runtime.h>
#include <cuda_fp16.h>
#include <stdint.h>
#include <math.h>

#define N_NODES 8192
#define F_IN    256
#define F_OUT   128

// ---------------- scratch (__device__ globals: allocation-free rule) --------
__device__ float g_Wh[N_NODES * F_OUT];                  // 4 MB
__device__ float g_wh1[N_NODES];
__device__ float g_wh2[N_NODES];
__device__ __half g_WhT[F_OUT * N_NODES];                // 2 MB  [c][j]
__device__ float g_part[2][N_NODES * F_OUT];             // 8 MB partial numerators
__device__ float g_denp[2][N_NODES];                     // partial denominators

// ---------------- helpers ---------------------------------------------------
__device__ __forceinline__ uint32_t smem_u32(const void* p) {
    uint32_t a;
    asm("{ .reg .u64 t; cvta.to.shared.u64 t, %1; cvt.u32.u64 %0, t; }"
        : "=r"(a) : "l"(p));
    return a;
}
__device__ __forceinline__ void ldsm4(uint32_t* r, uint32_t addr) {
    asm volatile("ldmatrix.sync.aligned.m8n8.x4.shared.b16 {%0,%1,%2,%3}, [%4];"
                 : "=r"(r[0]), "=r"(r[1]), "=r"(r[2]), "=r"(r[3]) : "r"(addr));
}
__device__ __forceinline__ void mma16816(float* d, const uint32_t* a,
                                         const uint32_t* b) {
    asm volatile(
        "mma.sync.aligned.m16n8k16.row.col.f32.f16.f16.f32 "
        "{%0,%1,%2,%3}, {%4,%5,%6,%7}, {%8,%9}, {%0,%1,%2,%3};"
        : "+f"(d[0]), "+f"(d[1]), "+f"(d[2]), "+f"(d[3])
        : "r"(a[0]), "r"(a[1]), "r"(a[2]), "r"(a[3]), "r"(b[0]), "r"(b[1]));
}
// pack two floats -> f16x2 (first arg = low half)
__device__ __forceinline__ uint32_t pack2h(float lo, float hi) {
    uint32_t r;
    asm("cvt.rn.f16x2.f32 %0, %1, %2;" : "=r"(r) : "f"(hi), "f"(lo));
    return r;
}

// ---------------------------------------------------------------------------
// k1: Wh = h @ W ; fused epilogue computes wh1 = Wh.a1, wh2 = Wh.a2
// ---------------------------------------------------------------------------
__global__ void __launch_bounds__(256) k1_gemm(const float* __restrict__ h,
                                               const float* __restrict__ W,
                                               const float* __restrict__ a) {
    __shared__ float sA[16][64];
    __shared__ float sB[16][128];
    const int t  = threadIdx.x;
    const int ty = t >> 4;
    const int tx = t & 15;
    const int row0 = blockIdx.x * 64;

    float acc[4][8];
#pragma unroll
    for (int m = 0; m < 4; m++)
#pragma unroll
        for (int n = 0; n < 8; n++) acc[m][n] = 0.f;

    for (int k0 = 0; k0 < F_IN; k0 += 16) {
#pragma unroll
        for (int it = 0; it < 4; it++) {
            int idx = t + it * 256;
            int r = idx >> 4, kk = idx & 15;
            sA[kk][r] = h[(row0 + r) * F_IN + k0 + kk];
        }
#pragma unroll
        for (int it = 0; it < 8; it++) {
            int idx = t + it * 256;
            int kk = idx >> 7, c = idx & 127;
            sB[kk][c] = W[(k0 + kk) * F_OUT + c];
        }
        __syncthreads();
#pragma unroll
        for (int kk = 0; kk < 16; kk++) {
            float av[4], bv[8];
#pragma unroll
            for (int m = 0; m < 4; m++) av[m] = sA[kk][ty * 4 + m];
#pragma unroll
            for (int n = 0; n < 8; n++) bv[n] = sB[kk][tx * 8 + n];
#pragma unroll
            for (int m = 0; m < 4; m++)
#pragma unroll
                for (int n = 0; n < 8; n++) acc[m][n] += av[m] * bv[n];
        }
        __syncthreads();
    }
    float a1v[8], a2v[8];
#pragma unroll
    for (int n = 0; n < 8; n++) {
        a1v[n] = a[tx * 8 + n];
        a2v[n] = a[F_OUT + tx * 8 + n];
    }
#pragma unroll
    for (int m = 0; m < 4; m++) {
        int r = row0 + ty * 4 + m;
#pragma unroll
        for (int n = 0; n < 8; n++)
            g_Wh[r * F_OUT + tx * 8 + n] = acc[m][n];
        float p1 = 0.f, p2 = 0.f;
#pragma unroll
        for (int n = 0; n < 8; n++) {
            p1 += acc[m][n] * a1v[n];
            p2 += acc[m][n] * a2v[n];
        }
#pragma unroll
        for (int off = 8; off > 0; off >>= 1) {
            p1 += __shfl_down_sync(0xffffffffu, p1, off);
            p2 += __shfl_down_sync(0xffffffffu, p2, off);
        }
        if (tx == 0) { g_wh1[r] = p1; g_wh2[r] = p2; }
    }
}

// ---------------------------------------------------------------------------
// k2: transpose Wh -> WhT (fp16)
// ---------------------------------------------------------------------------
__global__ void __launch_bounds__(256) k2_transpose() {
    __shared__ float tile[32][33];
    const int tx = threadIdx.x & 31;
    const int ty = threadIdx.x >> 5;
    const int nb = blockIdx.x * 32;
    const int fb = blockIdx.y * 32;
#pragma unroll
    for (int rr = ty; rr < 32; rr += 8)
        tile[rr][tx] = g_Wh[(nb + rr) * F_OUT + fb + tx];
    __syncthreads();
#pragma unroll
    for (int rr = ty; rr < 32; rr += 8) {
        float v = tile[tx][rr];
        g_WhT[(size_t)(fb + rr) * N_NODES + nb + tx] = __float2half_rn(v);
    }
}

// ---------------------------------------------------------------------------
// k3: fused attention, fp16 1-pass, double-buffered gen/MMA overlap
// grid = 128 = 64 row-blocks x 2 j-splits; BM=128, BK=128 per chunk
// ---------------------------------------------------------------------------
#define BK 128
#define NCHUNK 32
#define TSTRIDE 272                       // bytes per tile row (128*2 + 16)
#define TILE_BYTES (128 * TSTRIDE)        // 34816
#define STAGE_BYTES (2 * TILE_BYTES)      // 69632
#define OFF_S(s)  ((s) * STAGE_BYTES)
#define OFF_B(s)  ((s) * STAGE_BYTES + TILE_BYTES)
#define OFF_WH2   (2 * STAGE_BYTES)
#define SMEM3     (OFF_WH2 + 4096 * 4)    // 155,648 B

struct GenCtx {
    const __half* srcB;     // WhT row pointer (thread's row, j-base)
    const int*    adjp;     // adj row pointer
    const float*  sWh2;
    uint32_t sbase, genRow;
    float wh1r;
};

__device__ __forceinline__ void gen_chunk(const GenCtx& g, int c, int jb,
                                          char* sm, float& den) {
    const int s = c & 1;
#pragma unroll
    for (int kk = 0; kk < 8; kk++) {
        uint4 vh = *(const uint4*)(g.srcB + (size_t)c * BK + kk * 8);
        uint32_t o = g.genRow + (uint32_t)(jb + kk * 8) * 2;
        *(uint4*)(sm + OFF_B(s) + o) = vh;
    }
#pragma unroll
    for (int kk = 0; kk < 16; kk++) {
        int4 av = *(const int4*)(g.adjp + (size_t)c * BK + kk * 4);
        int jl = jb + kk * 4;
        float w0 = g.sWh2[c * BK + jl + 0], w1 = g.sWh2[c * BK + jl + 1];
        float w2 = g.sWh2[c * BK + jl + 2], w3 = g.sWh2[c * BK + jl + 3];
        float e0 = g.wh1r + w0, e1 = g.wh1r + w1;
        float e2 = g.wh1r + w2, e3 = g.wh1r + w3;
        e0 = fmaxf(e0, 0.2f * e0); e1 = fmaxf(e1, 0.2f * e1);
        e2 = fmaxf(e2, 0.2f * e2); e3 = fmaxf(e3, 0.2f * e3);
        float s0 = (av.x > 0) ? __expf(e0) : 0.f;
        float s1 = (av.y > 0) ? __expf(e1) : 0.f;
        float s2 = (av.z > 0) ? __expf(e2) : 0.f;
        float s3 = (av.w > 0) ? __expf(e3) : 0.f;
        den += (s0 + s1) + (s2 + s3);
        uint32_t h01 = pack2h(s0, s1), h23 = pack2h(s2, s3);
        uint32_t o = g.genRow + (uint32_t)jl * 2;
        asm volatile("st.shared.v2.b32 [%0], {%1,%2};"
                     :: "r"(g.sbase + OFF_S(s) + o), "r"(h01), "r"(h23));
    }
}

__global__ void __launch_bounds__(256, 1)
k3_attn(const int* __restrict__ adj) {
    extern __shared__ __align__(128) char sm[];
    const uint32_t sbase = smem_u32(sm);
    const int t   = threadIdx.x;
    const int wid = t >> 5;
    const int lid = t & 31;
    const int rb    = blockIdx.x >> 1;
    const int split = blockIdx.x & 1;
    const int row0  = rb * 128;
    const int jg0   = split * 4096;

    float* sWh2 = (float*)(sm + OFF_WH2);
#pragma unroll
    for (int i = 0; i < 16; i++)
        sWh2[t + i * 256] = g_wh2[jg0 + t + i * 256];

    // ---- generation-stage mapping: thread -> (row r, j-half) ----
    const int r    = t >> 1;
    const int half = t & 1;
    const int jb   = half * 64;
    float den = 0.f;

    GenCtx g;
    g.srcB   = g_WhT + (size_t)r * N_NODES + jg0 + jb;
    g.adjp   = adj + (size_t)(row0 + r) * N_NODES + jg0 + jb;
    g.sWh2   = sWh2;
    g.sbase  = sbase;
    g.genRow = (uint32_t)r * TSTRIDE;
    g.wh1r   = g_wh1[row0 + r];

    // ---- mma-stage mapping: 8 warps = 2(m) x 4(n); warp tile 64x32 ----
    const int warp_m = wid >> 2;
    const int warp_n = wid & 3;
    float d[4][4][4];
#pragma unroll
    for (int mf = 0; mf < 4; mf++)
#pragma unroll
        for (int nf = 0; nf < 4; nf++)
#pragma unroll
            for (int q = 0; q < 4; q++) d[mf][nf][q] = 0.f;

    const int gq = lid >> 3;
    const uint32_t aLane = (uint32_t)((gq & 1) * 8 + (lid & 7)) * TSTRIDE
                         + (uint32_t)((gq >> 1) * 8) * 2;
    const uint32_t bLane = (uint32_t)((gq >> 1) * 8 + (lid & 7)) * TSTRIDE
                         + (uint32_t)((gq & 1) * 8) * 2;
    const uint32_t aBase = sbase + (uint32_t)(warp_m * 64) * TSTRIDE + aLane;
    const uint32_t bBase = sbase + (uint32_t)(warp_n * 32) * TSTRIDE + bLane;

    __syncthreads();           // sWh2 ready
    gen_chunk(g, 0, jb, sm, den);
    __syncthreads();           // buf0 ready

    for (int c = 0; c < NCHUNK; c++) {
        const int s = c & 1;

        // gen next chunk into the other buffer (overlaps this chunk's MMA
        // via inter-warp slack; MMA(c-1) finished at last sync so the
        // target buffer is free)
        if (c + 1 < NCHUNK)
            gen_chunk(g, c + 1, jb, sm, den);

        // ---- MMA: D += S * B ----
#pragma unroll
        for (int ks = 0; ks < 8; ks++) {
            uint32_t as[4][4], bh[2][4];
#pragma unroll
            for (int mf = 0; mf < 4; mf++) {
                uint32_t ad = aBase + (uint32_t)(mf * 16) * TSTRIDE + ks * 32;
                ldsm4(as[mf], ad + OFF_S(s));
            }
#pragma unroll
            for (int nf2 = 0; nf2 < 2; nf2++) {
                uint32_t bd = bBase + (uint32_t)(nf2 * 16) * TSTRIDE + ks * 32;
                ldsm4(bh[nf2], bd + OFF_B(s));
            }
#pragma unroll
            for (int mf = 0; mf < 4; mf++)
#pragma unroll
                for (int nf = 0; nf < 4; nf++)
                    mma16816(d[mf][nf], as[mf], &bh[nf >> 1][(nf & 1) * 2]);
        }
        __syncthreads();
    }

    // ---- partial denominator (combine j-halves within lane pair) ----
    float dsum = den + __shfl_xor_sync(0xffffffffu, den, 1);
    if (half == 0) g_denp[split][row0 + r] = dsum;

    // ---- partial numerator: register tiles -> g_part ----
    const int qr = lid >> 2;
    const int qc = (lid & 3) * 2;
    float* base = g_part[split] + (size_t)(row0 + warp_m * 64 + qr) * F_OUT
                + warp_n * 32 + qc;
#pragma unroll
    for (int mf = 0; mf < 4; mf++) {
#pragma unroll
        for (int nf = 0; nf < 4; nf++) {
            float* p = base + (size_t)(mf * 16) * F_OUT + nf * 8;
            *(float2*)p = make_float2(d[mf][nf][0], d[mf][nf][1]);
            *(float2*)(p + 8 * F_OUT) = make_float2(d[mf][nf][2], d[mf][nf][3]);
        }
    }
}

// ---------------------------------------------------------------------------
// k4: combine splits, divide, ELU
// ---------------------------------------------------------------------------
__global__ void __launch_bounds__(256) k4_combine(float* __restrict__ out) {
    int tid = blockIdx.x * 256 + threadIdx.x;
    int e = tid * 8;
    int row = e >> 7;
    float dinv = 1.0f / (g_denp[0][row] + g_denp[1][row]);
    const float4* p0 = (const float4*)(g_part[0] + e);
    const float4* p1 = (const float4*)(g_part[1] + e);
    float4* o = (float4*)(out + e);
#pragma unroll
    for (int q = 0; q < 2; q++) {
        float4 x = p0[q], y = p1[q];
        float v0 = (x.x + y.x) * dinv;
        float v1 = (x.y + y.y) * dinv;
        float v2 = (x.z + y.z) * dinv;
        float v3 = (x.w + y.w) * dinv;
        float4 r;
        r.x = (v0 > 0.f) ? v0 : expm1f(v0);
        r.y = (v1 > 0.f) ? v1 : expm1f(v1);
        r.z = (v2 > 0.f) ? v2 : expm1f(v2);
        r.w = (v3 > 0.f) ? v3 : expm1f(v3);
        o[q] = r;
    }
}

// ---------------------------------------------------------------------------
extern "C" void kernel_launch(void* const* d_in, const int* in_sizes, int n_in,
                              void* d_out, int out_size) {
    const float* h   = (const float*)d_in[0];
    const int*   adj = (const int*)  d_in[1];
    const float* W   = (const float*)d_in[2];
    const float* a   = (const float*)d_in[3];
    float* out = (float*)d_out;

    cudaFuncSetAttribute(k3_attn, cudaFuncAttributeMaxDynamicSharedMemorySize, SMEM3);

    k1_gemm<<<N_NODES / 64, 256>>>(h, W, a);
    k2_transpose<<<dim3(N_NODES / 32, F_OUT / 32), 256>>>();
    k3_attn<<<128, 256, SMEM3>>>(adj);
    k4_combine<<<512, 256>>>(out);
}